// round 13
// baseline (speedup 1.0000x reference)
#include <cuda_runtime.h>
#include <cstdint>

// Sepconv: out[b,c,y,x] = sum_{i,j} in[b,c,5y+i,5x+j] * V[b,i,y,x] * H[b,j,y,x]
// B=8, C=3, F=5, HO=WO=256. HBM-bound: 184.6 MB compulsory; ~6.15 TB/s
// path-independent ceiling -> ~30us ncu floor (hit in R12 at 78.1% DRAM).
//
// R13: decouple work quantum from block count. 8192 blocks x 64 threads;
// each of the two warps is a fully independent R12-style unit (own 32-output
// chunk, own mbarriers, own 3x3.2KB strips, no __syncthreads). Keeps R12's
// steady-state DRAM efficiency with R11's (lower) per-block launch overhead.

#define B_ 8
#define C_ 3
#define F_ 5
#define HO_ 256
#define WO_ 256
#define HI_ (HO_ * F_)
#define WI_ (WO_ * F_)

#define QW_      32                       // outputs per warp
#define WPB_     2                        // warps per block
#define BW_      (QW_ * WPB_)             // 64 outputs per block
#define NQ_      (WO_ / BW_)              // 4 block-chunks per row
#define STRIP_W  (QW_ * F_)               // 160 floats per row chunk
#define ROW_BYTES (STRIP_W * 4)           // 640 B per bulk copy
#define TILE_FLOATS (F_ * STRIP_W)        // 800 floats = 3.2 KB per strip
#define TILE_BYTES  (TILE_FLOATS * 4)     // 3200
#define NT (QW_ * WPB_)                   // 64 threads

__device__ __forceinline__ void mbar_init(uint32_t mbar, uint32_t count) {
    asm volatile("mbarrier.init.shared.b64 [%0], %1;\n"
                 :: "r"(mbar), "r"(count) : "memory");
}
__device__ __forceinline__ void mbar_expect_tx(uint32_t mbar, uint32_t bytes) {
    asm volatile("mbarrier.arrive.expect_tx.shared.b64 _, [%0], %1;\n"
                 :: "r"(mbar), "r"(bytes) : "memory");
}
__device__ __forceinline__ void bulk_cp(uint32_t dst, const void* src,
                                        uint32_t bytes, uint32_t mbar) {
    asm volatile(
        "cp.async.bulk.shared::cta.global.mbarrier::complete_tx::bytes "
        "[%0], [%1], %2, [%3];\n"
        :: "r"(dst), "l"(src), "r"(bytes), "r"(mbar) : "memory");
}
__device__ __forceinline__ void mbar_wait(uint32_t mbar, uint32_t parity) {
    asm volatile(
        "{\n\t"
        ".reg .pred P;\n\t"
        "WAIT_%=:\n\t"
        "mbarrier.try_wait.parity.acquire.cta.shared::cta.b64 P, [%0], %1, 0x989680;\n\t"
        "@!P bra WAIT_%=;\n\t"
        "}"
        :: "r"(mbar), "r"(parity) : "memory");
}

__global__ __launch_bounds__(NT) void sepconv_tma13_kernel(
    const float* __restrict__ in,
    const float* __restrict__ V,
    const float* __restrict__ H,
    float* __restrict__ out)
{
    // Per-warp private regions: [warp][channel] strips and mbarriers.
    __shared__ __align__(16) float sdata[WPB_][C_ * TILE_FLOATS];  // 19.2 KB
    __shared__ __align__(8) unsigned long long mbar[WPB_][C_];

    const int tid  = threadIdx.x;                 // 0..63
    const int w    = tid >> 5;                    // warp 0/1
    const int lane = tid & 31;

    const int q = blockIdx.x & (NQ_ - 1);         // block chunk (0..3)
    const int y = (blockIdx.x >> 2) & (HO_ - 1);
    const int b = blockIdx.x >> 10;
    const int x0 = q * BW_ + w * QW_;             // this warp's 32 outputs

    const uint32_t sdata_u = (uint32_t)__cvta_generic_to_shared(&sdata[w][0]);
    const uint32_t mbar_u  = (uint32_t)__cvta_generic_to_shared(&mbar[w][0]);

    // Each warp initializes only its own barriers: warp-local ordering only.
    if (lane == 0) {
#pragma unroll
        for (int c = 0; c < C_; c++)
            mbar_init(mbar_u + 8u * c, 1);
        asm volatile("fence.proxy.async.shared::cta;\n" ::: "memory");
    }
    __syncwarp();

    // Lanes 0..2 of each warp post that warp's channel strips (640B extents).
    if (lane < C_) {
        const int c = lane;
        const long long base0 =
            ((long long)(b * C_) * HI_ + (long long)y * F_) * WI_
            + (long long)x0 * F_;
        mbar_expect_tx(mbar_u + 8u * c, TILE_BYTES);
        const float* strip = in + base0 + (long long)c * HI_ * WI_;
        const uint32_t dst = sdata_u + (uint32_t)(c * TILE_BYTES);
#pragma unroll
        for (int r = 0; r < F_; r++)
            bulk_cp(dst + (uint32_t)(r * ROW_BYTES),
                    strip + r * WI_, ROW_BYTES, mbar_u + 8u * c);
    }

    // Weights for (b, y, x0+lane): coalesced, overlap with TMA in flight.
    float v[F_], h[F_];
    {
        const int sb = (b * F_) * (HO_ * WO_) + y * WO_ + x0 + lane;
#pragma unroll
        for (int i = 0; i < F_; i++) {
            v[i] = V[sb + i * (HO_ * WO_)];
            h[i] = H[sb + i * (HO_ * WO_)];
        }
    }

#pragma unroll
    for (int c = 0; c < C_; c++) {
        mbar_wait(mbar_u + 8u * c, 0);            // acquire: strip c ready

        const float* s = &sdata[w][c * TILE_FLOATS];
        float acc = 0.0f;
#pragma unroll
        for (int i = 0; i < F_; i++) {
            const float* row = s + i * STRIP_W + lane * F_;
            float rs = 0.0f;
#pragma unroll
            for (int j = 0; j < F_; j++)
                rs = fmaf(row[j], h[j], rs);
            acc = fmaf(rs, v[i], acc);
        }
        __stcs(out + ((b * C_ + c) * HO_ + y) * WO_ + x0 + lane, acc);
    }
}

extern "C" void kernel_launch(void* const* d_in, const int* in_sizes, int n_in,
                              void* d_out, int out_size)
{
    const float* in  = (const float*)d_in[0];  // [8,3,1280,1280]
    const float* V   = (const float*)d_in[1];  // [8,5,256,256]
    const float* H   = (const float*)d_in[2];  // [8,5,256,256]
    float* out = (float*)d_out;                // [8,3,256,256]

    const int blocks = B_ * HO_ * NQ_;         // 8192: (b, y, chunk)
    sepconv_tma13_kernel<<<blocks, NT>>>(in, V, H, out);
}

// round 14
// speedup vs baseline: 1.0389x; 1.0389x over previous
#include <cuda_runtime.h>
#include <cstdint>

// Sepconv: out[b,c,y,x] = sum_{i,j} in[b,c,5y+i,5x+j] * V[b,i,y,x] * H[b,j,y,x]
// B=8, C=3, F=5, HO=WO=256. HBM-bound: 184.6 MB compulsory traffic.
// Best steady state (R13): 32-output independent-warp quantum -> 78.9% DRAM,
// 29.5us ncu. R14 keeps that quantum with 4 independent warps per block
// (4096 blocks x 128 threads) to shave per-block launch overhead.

#define B_ 8
#define C_ 3
#define F_ 5
#define HO_ 256
#define WO_ 256
#define HI_ (HO_ * F_)
#define WI_ (WO_ * F_)

#define QW_      32                       // outputs per warp
#define WPB_     4                        // independent warps per block
#define BW_      (QW_ * WPB_)             // 128 outputs per block
#define NQ_      (WO_ / BW_)              // 2 block-chunks per row
#define STRIP_W  (QW_ * F_)               // 160 floats per row chunk
#define ROW_BYTES (STRIP_W * 4)           // 640 B per bulk copy
#define TILE_FLOATS (F_ * STRIP_W)        // 800 floats = 3.2 KB per strip
#define TILE_BYTES  (TILE_FLOATS * 4)     // 3200
#define NT (QW_ * WPB_)                   // 128 threads

__device__ __forceinline__ void mbar_init(uint32_t mbar, uint32_t count) {
    asm volatile("mbarrier.init.shared.b64 [%0], %1;\n"
                 :: "r"(mbar), "r"(count) : "memory");
}
__device__ __forceinline__ void mbar_expect_tx(uint32_t mbar, uint32_t bytes) {
    asm volatile("mbarrier.arrive.expect_tx.shared.b64 _, [%0], %1;\n"
                 :: "r"(mbar), "r"(bytes) : "memory");
}
__device__ __forceinline__ void bulk_cp(uint32_t dst, const void* src,
                                        uint32_t bytes, uint32_t mbar) {
    asm volatile(
        "cp.async.bulk.shared::cta.global.mbarrier::complete_tx::bytes "
        "[%0], [%1], %2, [%3];\n"
        :: "r"(dst), "l"(src), "r"(bytes), "r"(mbar) : "memory");
}
__device__ __forceinline__ void mbar_wait(uint32_t mbar, uint32_t parity) {
    asm volatile(
        "{\n\t"
        ".reg .pred P;\n\t"
        "WAIT_%=:\n\t"
        "mbarrier.try_wait.parity.acquire.cta.shared::cta.b64 P, [%0], %1, 0x989680;\n\t"
        "@!P bra WAIT_%=;\n\t"
        "}"
        :: "r"(mbar), "r"(parity) : "memory");
}

__global__ __launch_bounds__(NT) void sepconv_tma14_kernel(
    const float* __restrict__ in,
    const float* __restrict__ V,
    const float* __restrict__ H,
    float* __restrict__ out)
{
    // Per-warp private regions: [warp][channel] strips and mbarriers.
    __shared__ __align__(16) float sdata[WPB_][C_ * TILE_FLOATS];  // 38.4 KB
    __shared__ __align__(8) unsigned long long mbar[WPB_][C_];

    const int tid  = threadIdx.x;                 // 0..127
    const int w    = tid >> 5;                    // warp 0..3
    const int lane = tid & 31;

    const int q = blockIdx.x & (NQ_ - 1);         // block chunk (0..1)
    const int y = (blockIdx.x >> 1) & (HO_ - 1);
    const int b = blockIdx.x >> 9;
    const int x0 = q * BW_ + w * QW_;             // this warp's 32 outputs

    const uint32_t sdata_u = (uint32_t)__cvta_generic_to_shared(&sdata[w][0]);
    const uint32_t mbar_u  = (uint32_t)__cvta_generic_to_shared(&mbar[w][0]);

    // Warp-local mbarrier init; only this warp ever touches these barriers.
    if (lane == 0) {
#pragma unroll
        for (int c = 0; c < C_; c++)
            mbar_init(mbar_u + 8u * c, 1);
        asm volatile("fence.proxy.async.shared::cta;\n" ::: "memory");
    }
    __syncwarp();

    // Lanes 0..2 post this warp's channel strips (640 B extents).
    if (lane < C_) {
        const int c = lane;
        const long long base0 =
            ((long long)(b * C_) * HI_ + (long long)y * F_) * WI_
            + (long long)x0 * F_;
        mbar_expect_tx(mbar_u + 8u * c, TILE_BYTES);
        const float* strip = in + base0 + (long long)c * HI_ * WI_;
        const uint32_t dst = sdata_u + (uint32_t)(c * TILE_BYTES);
#pragma unroll
        for (int r = 0; r < F_; r++)
            bulk_cp(dst + (uint32_t)(r * ROW_BYTES),
                    strip + r * WI_, ROW_BYTES, mbar_u + 8u * c);
    }

    // Weights for (b, y, x0+lane): coalesced, overlap with TMA in flight.
    float v[F_], h[F_];
    {
        const int sb = (b * F_) * (HO_ * WO_) + y * WO_ + x0 + lane;
#pragma unroll
        for (int i = 0; i < F_; i++) {
            v[i] = V[sb + i * (HO_ * WO_)];
            h[i] = H[sb + i * (HO_ * WO_)];
        }
    }

#pragma unroll
    for (int c = 0; c < C_; c++) {
        mbar_wait(mbar_u + 8u * c, 0);            // acquire: strip c ready

        const float* s = &sdata[w][c * TILE_FLOATS];
        float acc = 0.0f;
#pragma unroll
        for (int i = 0; i < F_; i++) {
            const float* row = s + i * STRIP_W + lane * F_;
            float rs = 0.0f;
#pragma unroll
            for (int j = 0; j < F_; j++)
                rs = fmaf(row[j], h[j], rs);
            acc = fmaf(rs, v[i], acc);
        }
        __stcs(out + ((b * C_ + c) * HO_ + y) * WO_ + x0 + lane, acc);
    }
}

extern "C" void kernel_launch(void* const* d_in, const int* in_sizes, int n_in,
                              void* d_out, int out_size)
{
    const float* in  = (const float*)d_in[0];  // [8,3,1280,1280]
    const float* V   = (const float*)d_in[1];  // [8,5,256,256]
    const float* H   = (const float*)d_in[2];  // [8,5,256,256]
    float* out = (float*)d_out;                // [8,3,256,256]

    const int blocks = B_ * HO_ * NQ_;         // 4096: (b, y, chunk)
    sepconv_tma14_kernel<<<blocks, NT>>>(in, V, H, out);
}